// round 17
// baseline (speedup 1.0000x reference)
#include <cuda_runtime.h>
#include <cuda_fp16.h>
#include <cstdint>
#include <math.h>

// Problem constants
constexpr int B_  = 4;
constexpr int S_  = 2048;
constexpr int D_  = 1024;
constexpr int H_  = 16;
constexpr int DK_ = 64;
constexpr int M_  = B_ * S_;   // 8192

// Scratch (device globals — no allocation allowed)
__device__ __half g_xq[(size_t)M_ * D_];   // fp16 copies of inputs
__device__ __half g_xk[(size_t)M_ * D_];
__device__ __half g_xv[(size_t)M_ * D_];
__device__ __half g_wq[(size_t)D_ * D_];
__device__ __half g_wk[(size_t)D_ * D_];
__device__ __half g_wv[(size_t)D_ * D_];
__device__ __half g_wo[(size_t)D_ * D_];
__device__ __half g_qh[(size_t)B_ * H_ * S_ * DK_];   // proj outputs [B,H,S,DK]
__device__ __half g_kh[(size_t)B_ * H_ * S_ * DK_];
__device__ __half g_vh[(size_t)B_ * H_ * S_ * DK_];
__device__ __half g_ctxh[(size_t)M_ * D_];            // flash output [B,S,D] fp16

// ---------------------------------------------------------------------------
// helpers (all non-suffixed PTX: works under generic sm_103 target)
// ---------------------------------------------------------------------------
__device__ __forceinline__ void mma_f16_16n8k16(float* c, const uint32_t* a,
                                                uint32_t b0, uint32_t b1) {
    asm volatile(
        "mma.sync.aligned.m16n8k16.row.col.f32.f16.f16.f32 "
        "{%0,%1,%2,%3}, {%4,%5,%6,%7}, {%8,%9}, {%0,%1,%2,%3};"
        : "+f"(c[0]), "+f"(c[1]), "+f"(c[2]), "+f"(c[3])
        : "r"(a[0]), "r"(a[1]), "r"(a[2]), "r"(a[3]), "r"(b0), "r"(b1));
}

__device__ __forceinline__ uint32_t smem_u32(const void* p) {
    uint32_t a;
    asm("{ .reg .u64 t; cvta.to.shared.u64 t, %1; cvt.u32.u64 %0, t; }"
        : "=r"(a) : "l"(p));
    return a;
}
__device__ __forceinline__ void cp_async16(uint32_t saddr, const void* g) {
    asm volatile("cp.async.ca.shared.global [%0], [%1], 16;"
                 :: "r"(saddr), "l"(g));
}
#define CP_COMMIT() asm volatile("cp.async.commit_group;" ::: "memory")
#define CP_WAIT0()  asm volatile("cp.async.wait_group 0;" ::: "memory")
#define CP_WAIT1()  asm volatile("cp.async.wait_group 1;" ::: "memory")
#define CP_WAIT2()  asm volatile("cp.async.wait_group 2;" ::: "memory")

__device__ __forceinline__ void ldsm_x4(uint32_t& r0, uint32_t& r1,
                                        uint32_t& r2, uint32_t& r3,
                                        uint32_t addr) {
    asm volatile("ldmatrix.sync.aligned.m8n8.x4.shared.b16 {%0,%1,%2,%3}, [%4];"
                 : "=r"(r0), "=r"(r1), "=r"(r2), "=r"(r3) : "r"(addr));
}
__device__ __forceinline__ void ldsm_x4_trans(uint32_t& r0, uint32_t& r1,
                                              uint32_t& r2, uint32_t& r3,
                                              uint32_t addr) {
    asm volatile("ldmatrix.sync.aligned.m8n8.x4.trans.shared.b16 {%0,%1,%2,%3}, [%4];"
                 : "=r"(r0), "=r"(r1), "=r"(r2), "=r"(r3) : "r"(addr));
}

// ---------------------------------------------------------------------------
// Pre-pass: fp32 -> fp16 for inputs + weights (R15 proven).
// ---------------------------------------------------------------------------
__global__ __launch_bounds__(256) void cvt_f16(
    const float* __restrict__ Q, const float* __restrict__ K,
    const float* __restrict__ V, const float* __restrict__ Wq,
    const float* __restrict__ Wk, const float* __restrict__ Wv,
    const float* __restrict__ Wo)
{
    const int y = blockIdx.y;
    const float* src;
    __half* dst;
    size_t n;
    switch (y) {
        case 0: src = Q;  dst = g_xq; n = (size_t)M_ * D_; break;
        case 1: src = K;  dst = g_xk; n = (size_t)M_ * D_; break;
        case 2: src = V;  dst = g_xv; n = (size_t)M_ * D_; break;
        case 3: src = Wq; dst = g_wq; n = (size_t)D_ * D_; break;
        case 4: src = Wk; dst = g_wk; n = (size_t)D_ * D_; break;
        case 5: src = Wv; dst = g_wv; n = (size_t)D_ * D_; break;
        default: src = Wo; dst = g_wo; n = (size_t)D_ * D_; break;
    }
    size_t i = ((size_t)blockIdx.x * 256 + threadIdx.x) * 8;
    if (i >= n) return;
    float4 a = *(const float4*)(src + i);
    float4 b = *(const float4*)(src + i + 4);
    __half2 h0 = __floats2half2_rn(a.x, a.y);
    __half2 h1 = __floats2half2_rn(a.z, a.w);
    __half2 h2 = __floats2half2_rn(b.x, b.y);
    __half2 h3 = __floats2half2_rn(b.z, b.w);
    uint4 u;
    u.x = *(uint32_t*)&h0; u.y = *(uint32_t*)&h1;
    u.z = *(uint32_t*)&h2; u.w = *(uint32_t*)&h3;
    *(uint4*)(dst + i) = u;
}

// ---------------------------------------------------------------------------
// FP16 GEMM v4: R15/R16 body, pipeline deepened to 4 STAGES via dynamic smem
// (static __shared__ capped us at 3 stages / 48KB). wait_group 2 in steady
// state -> two iterations of cp.async slack per barrier. Arithmetic and
// memory mappings byte-identical to v3 -> rel_err unchanged.
// which = which_base + blockIdx.z (QKV fused via gridDim.z = 3).
// ---------------------------------------------------------------------------
constexpr int GROW   = 32;                 // halves per smem row (64 B)
constexpr int GSTAGE = 128 * GROW;         // halves per tensor per stage
constexpr int GSTB   = GSTAGE * 2;         // bytes per tensor per stage (8192)
constexpr int GNST   = 4;                  // pipeline stages
constexpr int GSMEM  = 2 * GNST * GSTB;    // 65536 B dynamic

__global__ __launch_bounds__(256, 2) void gemm_f16(
    const float* __restrict__ b0p, const float* __restrict__ b1p,
    const float* __restrict__ b2p, float* __restrict__ dst, int which_base)
{
    extern __shared__ __half gsm[];

    const int z = blockIdx.z;
    const int which = which_base + z;
    const float* bias = (z == 0) ? b0p : (z == 1) ? b1p : b2p;

    const int tid = threadIdx.x;
    const int wid = tid >> 5;
    const int lane = tid & 31;
    const int m0 = blockIdx.y * 128;
    const int n0 = blockIdx.x * 128;
    const int warp_m = (wid & 3) * 32;
    const int warp_n = (wid >> 2) * 64;

    const __half* Ah = (which == 0) ? g_xq : (which == 1) ? g_xk
                     : (which == 2) ? g_xv : g_ctxh;
    const __half* Wh = (which == 0) ? g_wq : (which == 1) ? g_wk
                     : (which == 2) ? g_wv : g_wo;
    const __half* gA = Ah + (size_t)m0 * D_;
    const __half* gB = Wh + (size_t)n0 * D_;

    const uint32_t sAb = smem_u32(gsm);                     // A: stages 0..3
    const uint32_t sBb = sAb + (uint32_t)(GNST * GSTB);     // B: stages 0..3

    auto fill = [&](int st, int t) {
#pragma unroll
        for (int i = 0; i < 2; i++) {
            int idx = tid + i * 256;        // 0..511
            int row = idx >> 2;             // 0..127
            int ch = idx & 3;
            int sch = ch ^ ((row >> 1) & 3);
            uint32_t doff = (uint32_t)(st * GSTB + row * 64 + sch * 16);
            const __half* sa = gA + (size_t)row * D_ + t * 32 + ch * 8;
            const __half* sb = gB + (size_t)row * D_ + t * 32 + ch * 8;
            cp_async16(sAb + doff, sa);
            cp_async16(sBb + doff, sb);
        }
        CP_COMMIT();
    };

    float acc[2][8][4];
#pragma unroll
    for (int i = 0; i < 2; i++)
#pragma unroll
        for (int j = 0; j < 8; j++)
#pragma unroll
            for (int r = 0; r < 4; r++) acc[i][j][r] = 0.f;

    const int lm = lane >> 3;
    const int lr7 = lane & 7;
    const int rA = (lm & 1) * 8 + lr7;
    const int cAh = lm >> 1;
    const int rB = (lm >> 1) * 8 + lr7;
    const int cBh = lm & 1;

    uint32_t aOff[2][2], bOff[4][2];
#pragma unroll
    for (int t = 0; t < 2; t++)
#pragma unroll
        for (int s2 = 0; s2 < 2; s2++) {
            int row = warp_m + 16 * t + rA;
            int c = 2 * s2 + cAh;
            aOff[t][s2] = (uint32_t)(row * 64 + ((c ^ ((row >> 1) & 3)) * 16));
        }
#pragma unroll
    for (int jnp = 0; jnp < 4; jnp++)
#pragma unroll
        for (int s2 = 0; s2 < 2; s2++) {
            int row = warp_n + 16 * jnp + rB;
            int c = 2 * s2 + cBh;
            bOff[jnp][s2] = (uint32_t)(row * 64 + ((c ^ ((row >> 1) & 3)) * 16));
        }

    constexpr int T = D_ / 32;   // 32 iterations
    fill(0, 0);
    fill(1, 1);
    fill(2, 2);

    int st = 0;
    for (int t = 0; t < T; t++) {
        // fills issued through t+2; need fill(t) complete.
        if (t < T - 2)      { CP_WAIT2(); }
        else if (t < T - 1) { CP_WAIT1(); }
        else                { CP_WAIT0(); }
        __syncthreads();
        if (t + 3 < T) {
            int st3 = st + 3; if (st3 >= GNST) st3 -= GNST;
            fill(st3, t + 3);
        }

        const uint32_t aSt = sAb + (uint32_t)(st * GSTB);
        const uint32_t bSt = sBb + (uint32_t)(st * GSTB);

#pragma unroll
        for (int s2 = 0; s2 < 2; s2++) {
            uint32_t a[2][4];
            ldsm_x4(a[0][0], a[0][1], a[0][2], a[0][3], aSt + aOff[0][s2]);
            ldsm_x4(a[1][0], a[1][1], a[1][2], a[1][3], aSt + aOff[1][s2]);
#pragma unroll
            for (int jnp = 0; jnp < 4; jnp++) {
                uint32_t b0, b1, b2, b3;
                ldsm_x4(b0, b1, b2, b3, bSt + bOff[jnp][s2]);
                mma_f16_16n8k16(acc[0][2 * jnp], a[0], b0, b1);
                mma_f16_16n8k16(acc[1][2 * jnp], a[1], b0, b1);
                mma_f16_16n8k16(acc[0][2 * jnp + 1], a[0], b2, b3);
                mma_f16_16n8k16(acc[1][2 * jnp + 1], a[1], b2, b3);
            }
        }

        if (++st == GNST) st = 0;
    }

    const int r8 = lane >> 2;
    const int c2 = (lane & 3) * 2;
#pragma unroll
    for (int im = 0; im < 2; im++) {
#pragma unroll
        for (int jn = 0; jn < 8; jn++) {
            int n = n0 + warp_n + 8 * jn + c2;
            float bx = bias[n], by = bias[n + 1];
            int mA = m0 + warp_m + 16 * im + r8;
            int mB = mA + 8;
            float2 v0 = make_float2(acc[im][jn][0] + bx, acc[im][jn][1] + by);
            float2 v1 = make_float2(acc[im][jn][2] + bx, acc[im][jn][3] + by);
            if (which < 3) {
                __half* outh = (which == 0) ? g_qh : (which == 1) ? g_kh : g_vh;
                __half2 h0 = __floats2half2_rn(v0.x, v0.y);
                __half2 h1 = __floats2half2_rn(v1.x, v1.y);
                int h = n >> 6, dk = n & 63;
                int bA = mA >> 11, sA = mA & (S_ - 1);
                int bB = mB >> 11, sB = mB & (S_ - 1);
                *(__half2*)&outh[(((size_t)(bA * H_ + h) * S_ + sA) << 6) + dk] = h0;
                *(__half2*)&outh[(((size_t)(bB * H_ + h) * S_ + sB) << 6) + dk] = h1;
            } else {
                *(float2*)&dst[(size_t)mA * D_ + n] = v0;
                *(float2*)&dst[(size_t)mB * D_ + n] = v1;
            }
        }
    }
}

// ---------------------------------------------------------------------------
// Flash attention v8 (R16 proven: BQ=128, 2 CTAs/SM) — UNCHANGED.
// ---------------------------------------------------------------------------
constexpr int QBYTES = 128 * 144;
constexpr int KSTAGE = 64 * 144;
constexpr int VSTAGE = 64 * 144;
constexpr int FSMEM  = QBYTES + 2 * KSTAGE + 2 * VSTAGE;  // 55296

__global__ __launch_bounds__(256, 2) void flash_f16()
{
    extern __shared__ char smc[];
    char* sQ = smc;
    char* sK = sQ + QBYTES;
    char* sV = sK + 2 * KSTAGE;

    const uint32_t sqb = smem_u32(sQ);
    const uint32_t skb = smem_u32(sK);
    const uint32_t svb = smem_u32(sV);

    const int tid = threadIdx.x;
    const int wid = tid >> 5;
    const int lane = tid & 31;
    const int r8 = lane >> 2;
    const int c4 = lane & 3;
    const int lm = lane >> 3;
    const int lr7 = lane & 7;

    const uint32_t laneA =
        (uint32_t)(((lm & 1) * 8 + lr7) * 144 + (lm >> 1) * 16);
    const uint32_t laneB =
        (uint32_t)(((lm >> 1) * 8 + lr7) * 144 + (lm & 1) * 16);
    const uint32_t laneV =
        (uint32_t)(((lm & 1) * 8 + lr7) * 144 + (lm >> 1) * 16);

    const int q0 = blockIdx.x * 128;
    const int h = blockIdx.y;
    const int b = blockIdx.z;
    const size_t base = (size_t)(b * H_ + h) * S_ * DK_;
    const __half* qg = g_qh + base + (size_t)q0 * DK_;
    const __half* kg = g_kh + base;
    const __half* vg = g_vh + base;

    const int wr = wid * 16;

    auto issue_chunk = [&](int kb, int st) {
#pragma unroll
        for (int i = 0; i < 2; i++) {
            int idx = tid + i * 256;
            int row = idx >> 3;
            int c16 = (idx & 7) * 16;
            cp_async16(skb + (uint32_t)(st * KSTAGE + row * 144) + c16,
                       kg + (size_t)(kb + row) * DK_ + (idx & 7) * 8);
            cp_async16(svb + (uint32_t)(st * VSTAGE + row * 144) + c16,
                       vg + (size_t)(kb + row) * DK_ + (idx & 7) * 8);
        }
        CP_COMMIT();
    };

#pragma unroll
    for (int i = 0; i < 4; i++) {
        int idx = tid + i * 256;
        int row = idx >> 3;
        int c16 = (idx & 7) * 16;
        cp_async16(sqb + (uint32_t)(row * 144) + c16,
                   qg + (size_t)row * DK_ + (idx & 7) * 8);
    }
    CP_COMMIT();
    issue_chunk(0, 0);

    CP_WAIT1();
    __syncthreads();

    uint32_t aq[4][4];
    {
        const __half2 hs = __half2half2(__float2half_rn(0.125f));
#pragma unroll
        for (int kc = 0; kc < 4; kc++) {
            uint32_t addr = sqb + (uint32_t)(wr * 144 + kc * 32) + laneA;
            ldsm_x4(aq[kc][0], aq[kc][1], aq[kc][2], aq[kc][3], addr);
#pragma unroll
            for (int r = 0; r < 4; r++) {
                __half2 v = *(__half2*)&aq[kc][r];
                v = __hmul2(v, hs);
                aq[kc][r] = *(uint32_t*)&v;
            }
        }
    }

    float m0r = -1e30f, m1r = -1e30f, l0 = 0.f, l1 = 0.f;
    float o[8][4];
#pragma unroll
    for (int j = 0; j < 8; j++)
#pragma unroll
        for (int r = 0; r < 4; r++) o[j][r] = 0.f;

    for (int c = 0; c < S_ / 64; c++) {
        const int st = c & 1;
        CP_WAIT0();
        __syncthreads();
        if (c + 1 < S_ / 64) issue_chunk((c + 1) * 64, st ^ 1);

        const uint32_t skc = skb + (uint32_t)(st * KSTAGE) + laneB;
        const uint32_t svc = svb + (uint32_t)(st * VSTAGE) + laneV;

        float s[8][4];
#pragma unroll
        for (int j = 0; j < 8; j++)
#pragma unroll
            for (int r = 0; r < 4; r++) s[j][r] = 0.f;

#pragma unroll
        for (int kc = 0; kc < 4; kc++) {
#pragma unroll
            for (int jnp = 0; jnp < 4; jnp++) {
                uint32_t k0, k1, k2, k3;
                ldsm_x4(k0, k1, k2, k3,
                        skc + (uint32_t)(jnp * 16 * 144 + kc * 32));
                mma_f16_16n8k16(s[2 * jnp], aq[kc], k0, k1);
                mma_f16_16n8k16(s[2 * jnp + 1], aq[kc], k2, k3);
            }
        }

        uint32_t ph[8][2];
        {
            float mx0 = -1e30f, mx1 = -1e30f;
#pragma unroll
            for (int jn = 0; jn < 8; jn++) {
                mx0 = fmaxf(mx0, fmaxf(s[jn][0], s[jn][1]));
                mx1 = fmaxf(mx1, fmaxf(s[jn][2], s[jn][3]));
            }
            mx0 = fmaxf(mx0, __shfl_xor_sync(0xffffffffu, mx0, 1));
            mx0 = fmaxf(mx0, __shfl_xor_sync(0xffffffffu, mx0, 2));
            mx1 = fmaxf(mx1, __shfl_xor_sync(0xffffffffu, mx1, 1));
            mx1 = fmaxf(mx1, __shfl_xor_sync(0xffffffffu, mx1, 2));
            float mn0 = fmaxf(m0r, mx0), mn1 = fmaxf(m1r, mx1);
            float alpha0 = __expf(m0r - mn0);
            float alpha1 = __expf(m1r - mn1);
            float sum0 = 0.f, sum1 = 0.f;
#pragma unroll
            for (int jn = 0; jn < 8; jn++) {
                float e0 = __expf(s[jn][0] - mn0);
                float e1 = __expf(s[jn][1] - mn0);
                float e2 = __expf(s[jn][2] - mn1);
                float e3 = __expf(s[jn][3] - mn1);
                sum0 += e0 + e1;
                sum1 += e2 + e3;
                __half2 hA = __floats2half2_rn(e0, e1);
                __half2 hB = __floats2half2_rn(e2, e3);
                ph[jn][0] = *(uint32_t*)&hA;
                ph[jn][1] = *(uint32_t*)&hB;
            }
            sum0 += __shfl_xor_sync(0xffffffffu, sum0, 1);
            sum0 += __shfl_xor_sync(0xffffffffu, sum0, 2);
            sum1 += __shfl_xor_sync(0xffffffffu, sum1, 1);
            sum1 += __shfl_xor_sync(0xffffffffu, sum1, 2);
            l0 = l0 * alpha0 + sum0;
            l1 = l1 * alpha1 + sum1;
            m0r = mn0;
            m1r = mn1;
#pragma unroll
            for (int jn = 0; jn < 8; jn++) {
                o[jn][0] *= alpha0; o[jn][1] *= alpha0;
                o[jn][2] *= alpha1; o[jn][3] *= alpha1;
            }
        }

#pragma unroll
        for (int kc = 0; kc < 4; kc++) {
            uint32_t ap[4] = { ph[2 * kc][0], ph[2 * kc][1],
                               ph[2 * kc + 1][0], ph[2 * kc + 1][1] };
#pragma unroll
            for (int jnp = 0; jnp < 4; jnp++) {
                uint32_t v0, v1, v2, v3;
                ldsm_x4_trans(v0, v1, v2, v3,
                              svc + (uint32_t)(kc * 16 * 144 + jnp * 32));
                mma_f16_16n8k16(o[2 * jnp], ap, v0, v1);
                mma_f16_16n8k16(o[2 * jnp + 1], ap, v2, v3);
            }
        }
    }

    {
        float inv0 = 1.0f / l0, inv1 = 1.0f / l1;
        int row0 = q0 + wr + r8;
        int row1 = row0 + 8;
        size_t g0 = ((size_t)b * S_ + row0) * D_ + h * DK_;
        size_t g1 = ((size_t)b * S_ + row1) * D_ + h * DK_;
#pragma unroll
        for (int jn = 0; jn < 8; jn++) {
            int col = 8 * jn + 2 * c4;
            *(__half2*)&g_ctxh[g0 + col] =
                __floats2half2_rn(o[jn][0] * inv0, o[jn][1] * inv0);
            *(__half2*)&g_ctxh[g1 + col] =
                __floats2half2_rn(o[jn][2] * inv1, o[jn][3] * inv1);
        }
    }
}

// ---------------------------------------------------------------------------
// Launch
// ---------------------------------------------------------------------------
extern "C" void kernel_launch(void* const* d_in, const int* in_sizes, int n_in,
                              void* d_out, int out_size)
{
    const float* Q  = (const float*)d_in[0];
    const float* K  = (const float*)d_in[1];
    const float* V  = (const float*)d_in[2];
    const float* Wq = (const float*)d_in[3];
    const float* bq = (const float*)d_in[4];
    const float* Wk = (const float*)d_in[5];
    const float* bk = (const float*)d_in[6];
    const float* Wv = (const float*)d_in[7];
    const float* bv = (const float*)d_in[8];
    const float* Wo = (const float*)d_in[9];
    const float* bo = (const float*)d_in[10];
    float* out = (float*)d_out;

    cudaFuncSetAttribute(gemm_f16,
                         cudaFuncAttributeMaxDynamicSharedMemorySize, GSMEM);
    cudaFuncSetAttribute(flash_f16,
                         cudaFuncAttributeMaxDynamicSharedMemorySize, FSMEM);

    cvt_f16<<<dim3(4096, 7), 256>>>(Q, K, V, Wq, Wk, Wv, Wo);

    gemm_f16<<<dim3(D_ / 128, M_ / 128, 3), 256, GSMEM>>>(bq, bk, bv,
                                                          nullptr, 0);

    flash_f16<<<dim3(S_ / 128, H_, B_), 256, FSMEM>>>();

    gemm_f16<<<dim3(D_ / 128, M_ / 128, 1), 256, GSMEM>>>(bo, bo, bo, out, 3);
}